// round 15
// baseline (speedup 1.0000x reference)
#include <cuda_runtime.h>
#include <cuda_fp16.h>
#include <cstdint>

// CFConv fused, FP16 mma (m16n8k16). Persistent CTAs; warp-private cp.async
// ring with RING = 8 = chunks/tile: slot c always holds chunk c, refilled with
// the NEXT tile's chunk c at consume time -> one full tile (4KB/warp) of DRAM
// loads in flight through ALL phases (GEMM2/epilogue included), zero stall
// waits in steady state. Weights in smem once per CTA. nf rows L1-prefetched
// a tile ahead of the epilogue gather.
//
// h  = softplus_b05(rbf @ W1^T + b1)   [E,128] x [64,128]^T -> [E,64]
// g  = h @ W2^T + b2                   [E,64]  x [64,64]^T  -> [E,64]
// out[dst[e]] += node_feats[src[e]] * h[e]... (gated by nf[src], summed by dst)

constexpr int BM      = 128;    // edges per tile
constexpr int THREADS = 128;    // 4 warps x 32 edges

constexpr int W1S  = 68;    // half2 words per W1 row (64 + 4 pad)
constexpr int W2S  = 36;    // half2 words per W2 row (32 + 4 pad)
constexpr int AROW = 20;    // fp32 words per staged A row (16 + 4 pad)
constexpr int RING = 8;     // slots == chunks per tile (compile-time slots)

__device__ uint32_t g_W1h[64 * W1S];
__device__ uint32_t g_W2h[64 * W2S];

constexpr int OFF_W1 = 0;
constexpr int OFF_W2 = OFF_W1 + 64 * W1S;        // 4352 words
constexpr int OFF_A  = OFF_W2 + 64 * W2S;        // 6656 words
constexpr int SLOTW  = 32 * AROW;                // 640 words per slot
constexpr int SLOTB  = SLOTW * 4;                // 2560 B
constexpr int AWARP  = RING * SLOTW;             // 5120 words per warp
constexpr int SMEM_WORDS = OFF_A + 4 * AWARP;    // 27136
constexpr int SMEM_BYTES = SMEM_WORDS * 4;       // 108544 -> 2 CTAs/SM

// setup: zero output + convert weights to fp16 padded layout
__global__ void setup_kernel(float4* out4, int n4,
                             const float* __restrict__ W1,
                             const float* __restrict__ W2) {
    int i = blockIdx.x * blockDim.x + threadIdx.x;
    if (i < n4) out4[i] = make_float4(0.f, 0.f, 0.f, 0.f);
    if (i < 64 * W1S) {
        int row = i / W1S, c = i % W1S;
        uint32_t v = 0;
        if (c < 64) {
            __half2 h = __floats2half2_rn(W1[row * 128 + 2 * c], W1[row * 128 + 2 * c + 1]);
            v = *reinterpret_cast<uint32_t*>(&h);
        }
        g_W1h[i] = v;
    }
    if (i < 64 * W2S) {
        int row = i / W2S, c = i % W2S;
        uint32_t v = 0;
        if (c < 32) {
            __half2 h = __floats2half2_rn(W2[row * 64 + 2 * c], W2[row * 64 + 2 * c + 1]);
            v = *reinterpret_cast<uint32_t*>(&h);
        }
        g_W2h[i] = v;
    }
}

__device__ __forceinline__ float softplus_b05(float x) {
    float hx = 0.5f * x;
    return (hx > 14.0f) ? x : 2.0f * __logf(1.0f + __expf(hx));
}

__device__ __forceinline__ uint32_t pack_h2(float lo, float hi) {
    __half2 p = __floats2half2_rn(lo, hi);
    return *reinterpret_cast<uint32_t*>(&p);
}

__device__ __forceinline__ void mma_f16(float c[4], const uint32_t a[4],
                                        uint32_t b0, uint32_t b1) {
    asm volatile(
        "mma.sync.aligned.m16n8k16.row.col.f32.f16.f16.f32 "
        "{%0,%1,%2,%3}, {%4,%5,%6,%7}, {%8,%9}, {%0,%1,%2,%3};"
        : "+f"(c[0]), "+f"(c[1]), "+f"(c[2]), "+f"(c[3])
        : "r"(a[0]), "r"(a[1]), "r"(a[2]), "r"(a[3]), "r"(b0), "r"(b1));
}

__device__ __forceinline__ void ldsm_x4(uint32_t r[4], uint32_t addr) {
    asm volatile("ldmatrix.sync.aligned.m8n8.x4.shared.b16 {%0,%1,%2,%3}, [%4];"
                 : "=r"(r[0]), "=r"(r[1]), "=r"(r[2]), "=r"(r[3]) : "r"(addr));
}

__device__ __forceinline__ void cp_async16(uint32_t saddr, const void* gsrc) {
    asm volatile("cp.async.cg.shared.global [%0], [%1], 16;"
                 :: "r"(saddr), "l"(gsrc));
}

__device__ __forceinline__ float2 lds_f2(uint32_t addr) {
    float2 v;
    asm volatile("ld.shared.v2.f32 {%0,%1}, [%2];"
                 : "=f"(v.x), "=f"(v.y) : "r"(addr));
    return v;
}

__device__ __forceinline__ void prefetch_l1(const void* p) {
    asm volatile("prefetch.global.L1 [%0];" :: "l"(p));
}

__global__ void __launch_bounds__(THREADS, 2) cfconv_f16_kernel(
    const float* __restrict__ rbf,   // [E,128]
    const float* __restrict__ nf,    // [N,64]
    const int*   __restrict__ src,   // [E]
    const int*   __restrict__ dst,   // [E]
    const float* __restrict__ b1,    // [64]
    const float* __restrict__ b2,    // [64]
    float*       __restrict__ out,   // [N,64]
    int E, int ntiles)
{
    extern __shared__ uint32_t smem[];

    const int tid  = threadIdx.x;
    const int lane = tid & 31;
    const int warp = tid >> 5;
    const int gr   = lane >> 2;
    const int gc   = lane & 3;
    const int wrow = warp * 32;
    const int gstride = gridDim.x;
    const unsigned FULL = 0xffffffffu;
    const bool odd = (gc & 1);
    const char* rbfB = (const char*)rbf;

    const uint32_t sbase = (uint32_t)__cvta_generic_to_shared(smem);

    // ---- group: weights, loaded ONCE per persistent CTA ----
    for (int i = tid; i < 1088; i += THREADS)
        cp_async16(sbase + OFF_W1 * 4 + i * 16, (const char*)g_W1h + i * 16);
    for (int i = tid; i < 576; i += THREADS)
        cp_async16(sbase + OFF_W2 * 4 + i * 16, (const char*)g_W2h + i * 16);
    asm volatile("cp.async.commit_group;");

    // ---- ring geometry: lane covers rows (lane>>2)+8i (i=0..3), 16B each ----
    const uint32_t aBase = sbase + (OFF_A + warp * AWARP) * 4;
    const int lrow = lane >> 2;
    uint32_t sdst4[4];
    #pragma unroll
    for (int i = 0; i < 4; i++)
        sdst4[i] = aBase + ((lrow + 8 * i) * AROW + (lane & 3) * 4) * 4;

    // ---- B-fragment ldsm addresses ----
    const int lb = ((lane >> 4) << 3) | (lane & 7);
    const int sbyt = ((lane >> 3) & 1) * 16;
    uint32_t bW1a[4], bW2a[4];
    #pragma unroll
    for (int p = 0; p < 4; p++) {
        bW1a[p] = sbase + (OFF_W1 + (p * 16 + lb) * W1S) * 4 + sbyt;
        bW2a[p] = sbase + (OFF_W2 + (p * 16 + lb) * W2S) * 4 + sbyt;
    }

    // ---- first tile's rbf byte-offsets; prime ALL 8 slots (one full tile) ----
    int tile = blockIdx.x;
    uint32_t offN[4];
    #pragma unroll
    for (int i = 0; i < 4; i++) {
        long e = (long)tile * BM + wrow + lrow + 8 * i;
        long ec = (e < E) ? e : 0;
        offN[i] = (uint32_t)(ec * 512) + (lane & 3) * 16;
    }
    #pragma unroll
    for (int c = 0; c < RING; c++) {
        #pragma unroll
        for (int i = 0; i < 4; i++)
            cp_async16(sdst4[i] + c * SLOTB, rbfB + offN[i] + c * 64);
        asm volatile("cp.async.commit_group;");
    }

    asm volatile("cp.async.wait_group 8;");   // weights done (8 chunk groups may fly)
    __syncthreads();                          // weights visible block-wide

    for (; tile < ntiles; tile += gstride) {
        // current tile's offsets were loaded as offN last iteration; compute next's
        uint32_t offC[4];
        #pragma unroll
        for (int i = 0; i < 4; i++) offC[i] = offN[i];
        {
            int tnext = tile + gstride;
            int tsrc = (tnext < ntiles) ? tnext : tile;   // phantom reload on last
            #pragma unroll
            for (int i = 0; i < 4; i++) {
                long e = (long)tsrc * BM + wrow + lrow + 8 * i;
                long ec = (e < E) ? e : 0;
                offN[i] = (uint32_t)(ec * 512) + (lane & 3) * 16;
            }
        }

        // lane-private edge indices; prefetch this tile's nf row into L1
        const long eMine = (long)tile * BM + wrow + lane;
        const bool valMine = (eMine < E);
        int myS = valMine ? src[eMine] : 0;
        int myD = valMine ? dst[eMine] : 0;
        {
            const char* nfp = (const char*)(nf + (long)myS * 64);
            prefetch_l1(nfp);
            prefetch_l1(nfp + 128);
        }

        // ---- GEMM1: 8 chunks of K=16; slot c refilled with NEXT tile chunk c ----
        float acc[2][8][4] = {};
        #pragma unroll
        for (int c = 0; c < 8; c++) {
            asm volatile("cp.async.wait_group 7;");   // group for chunk c done
            __syncwarp();
            const uint32_t bo = c * SLOTB;

            uint32_t a[2][4];
            #pragma unroll
            for (int mt = 0; mt < 2; mt++) {
                const uint32_t r0 = aBase + bo + ((mt * 16 + gr) * AROW + 2 * gc) * 4;
                const uint32_t r1 = r0 + 8 * AROW * 4;
                float2 f0 = lds_f2(r0);
                float2 f1 = lds_f2(r1);
                float2 f2 = lds_f2(r0 + 32);
                float2 f3 = lds_f2(r1 + 32);
                a[mt][0] = pack_h2(f0.x, f0.y);
                a[mt][1] = pack_h2(f1.x, f1.y);
                a[mt][2] = pack_h2(f2.x, f2.y);
                a[mt][3] = pack_h2(f3.x, f3.y);
            }

            __syncwarp();   // all lanes done reading slot c: refill with next tile
            #pragma unroll
            for (int i = 0; i < 4; i++)
                cp_async16(sdst4[i] + bo, rbfB + offN[i] + c * 64);
            asm volatile("cp.async.commit_group;");

            #pragma unroll
            for (int p = 0; p < 4; p++) {
                uint32_t bb[4];
                ldsm_x4(bb, bW1a[p] + c * 32);
                mma_f16(acc[0][2 * p],     a[0], bb[0], bb[1]);
                mma_f16(acc[1][2 * p],     a[1], bb[0], bb[1]);
                mma_f16(acc[0][2 * p + 1], a[0], bb[2], bb[3]);
                mma_f16(acc[1][2 * p + 1], a[1], bb[2], bb[3]);
            }
        }

        // ---- bias + softplus + pack: GEMM1 C-frags -> GEMM2 A-frags ----
        uint32_t hA[2][4][4];
        #pragma unroll
        for (int kt = 0; kt < 4; kt++) {
            float bA0 = __ldg(b1 + kt * 16 + 2 * gc);
            float bA1 = __ldg(b1 + kt * 16 + 2 * gc + 1);
            float bB0 = __ldg(b1 + kt * 16 + 8 + 2 * gc);
            float bB1 = __ldg(b1 + kt * 16 + 8 + 2 * gc + 1);
            #pragma unroll
            for (int mt = 0; mt < 2; mt++) {
                const float* cA = acc[mt][2 * kt];
                const float* cB = acc[mt][2 * kt + 1];
                hA[mt][kt][0] = pack_h2(softplus_b05(cA[0] + bA0), softplus_b05(cA[1] + bA1));
                hA[mt][kt][1] = pack_h2(softplus_b05(cA[2] + bA0), softplus_b05(cA[3] + bA1));
                hA[mt][kt][2] = pack_h2(softplus_b05(cB[0] + bB0), softplus_b05(cB[1] + bB1));
                hA[mt][kt][3] = pack_h2(softplus_b05(cB[2] + bB0), softplus_b05(cB[3] + bB1));
            }
        }

        // ---- GEMM2: K=64, 4 chunks of 16 ----
        float acc2[2][8][4] = {};
        #pragma unroll
        for (int kt = 0; kt < 4; kt++) {
            #pragma unroll
            for (int p = 0; p < 4; p++) {
                uint32_t bb[4];
                ldsm_x4(bb, bW2a[p] + kt * 32);
                mma_f16(acc2[0][2 * p],     hA[0][kt], bb[0], bb[1]);
                mma_f16(acc2[1][2 * p],     hA[1][kt], bb[0], bb[1]);
                mma_f16(acc2[0][2 * p + 1], hA[0][kt], bb[2], bb[3]);
                mma_f16(acc2[1][2 * p + 1], hA[1][kt], bb[2], bb[3]);
            }
        }

        // ---- epilogue (next tile fully in flight): gate by nf[src] (L1-warm),
        //      vector red scatter to out[dst] ----
        #pragma unroll
        for (int mt = 0; mt < 2; mt++) {
            int rowl = mt * 16 + gr + (odd ? 8 : 0);
            int s = __shfl_sync(FULL, myS, rowl);
            int d = __shfl_sync(FULL, myD, rowl);
            bool valid = ((long)tile * BM + wrow + rowl < E);
            const float* nfr = nf + (long)s * 64;
            float* outr = out + (long)d * 64;
            #pragma unroll
            for (int nt = 0; nt < 8; nt++) {
                float bc0 = __ldg(b2 + nt * 8 + 2 * gc);
                float bc1 = __ldg(b2 + nt * 8 + 2 * gc + 1);
                float g0 = acc2[mt][nt][0] + bc0, g1 = acc2[mt][nt][1] + bc1;
                float g2 = acc2[mt][nt][2] + bc0, g3 = acc2[mt][nt][3] + bc1;
                float x0 = __shfl_xor_sync(FULL, g0, 1);
                float x1 = __shfl_xor_sync(FULL, g1, 1);
                float x2 = __shfl_xor_sync(FULL, g2, 1);
                float x3 = __shfl_xor_sync(FULL, g3, 1);
                float v0, v1, v2, v3;
                if (odd) { v0 = x2; v1 = x3; v2 = g2; v3 = g3; }
                else     { v0 = g0; v1 = g1; v2 = x0; v3 = x1; }
                int col = nt * 8 + 4 * (gc >> 1);
                if (valid) {
                    float4 nf4 = *(const float4*)(nfr + col);
                    v0 *= nf4.x; v1 *= nf4.y; v2 *= nf4.z; v3 *= nf4.w;
                    asm volatile("red.global.add.v4.f32 [%0], {%1,%2,%3,%4};"
                                 :: "l"(outr + col), "f"(v0), "f"(v1), "f"(v2), "f"(v3)
                                 : "memory");
                }
            }
        }
    }
}

extern "C" void kernel_launch(void* const* d_in, const int* in_sizes, int n_in,
                              void* d_out, int out_size) {
    const float* rbf = (const float*)d_in[0];
    const float* nf  = (const float*)d_in[1];
    const int*   src = (const int*)d_in[2];
    const int*   dst = (const int*)d_in[3];
    const float* W1  = (const float*)d_in[4];
    const float* b1  = (const float*)d_in[5];
    const float* W2  = (const float*)d_in[6];
    const float* b2  = (const float*)d_in[7];
    float* out = (float*)d_out;

    const int E = in_sizes[2];
    const int ntiles = (E + BM - 1) / BM;

    cudaFuncSetAttribute(cfconv_f16_kernel,
                         cudaFuncAttributeMaxDynamicSharedMemorySize, SMEM_BYTES);

    int n4 = out_size / 4;
    setup_kernel<<<(n4 + 255) / 256, 256>>>((float4*)out, n4, W1, W2);

    int grid = 148 * 2;
    if (grid > ntiles) grid = ntiles;
    cfconv_f16_kernel<<<grid, THREADS, SMEM_BYTES>>>(
        rbf, nf, src, dst, b1, b2, out, E, ntiles);
}

// round 16
// speedup vs baseline: 2.1071x; 2.1071x over previous
#include <cuda_runtime.h>
#include <cuda_fp16.h>
#include <cstdint>

// CFConv fused, FP16 mma (m16n8k16). Persistent CTAs grid-stride over
// 128-edge tiles; weights in smem ONCE per CTA; rbf streamed via a
// warp-private cp.async ring (depth 3, runtime slot) running continuously
// ACROSS tile boundaries. NEW vs R9: node_feats pre-converted to fp16
// (halves the scattered-gather L1/L2 traffic) + L1 prefetch of each lane's
// nf row a full tile ahead of the epilogue.
//
// h  = softplus_b05(rbf @ W1^T + b1)   [E,128] x [64,128]^T -> [E,64]
// g  = h @ W2^T + b2                   [E,64]  x [64,64]^T  -> [E,64]
// out[dst[e]] += node_feats[src[e]] * g[e]

constexpr int BM      = 128;
constexpr int THREADS = 128;

constexpr int W1S  = 68;    // half2 words per W1 row (64 + 4 pad)
constexpr int W2S  = 36;    // half2 words per W2 row (32 + 4 pad)
constexpr int AROW = 20;    // fp32 words per A row (16 + 4 pad)
constexpr int RING = 3;     // chunks in flight per warp

constexpr int MAX_NODES = 65536;   // dataset: 50000

__device__ uint32_t g_W1h[64 * W1S];
__device__ uint32_t g_W2h[64 * W2S];
__device__ uint32_t g_nfh[MAX_NODES * 32];   // nf as half2: 32 words per row

constexpr int OFF_W1 = 0;
constexpr int OFF_W2 = OFF_W1 + 64 * W1S;        // 4352 words
constexpr int OFF_A  = OFF_W2 + 64 * W2S;        // 6656 words
constexpr int SLOTW  = 32 * AROW;                // 640 words per ring slot
constexpr int AWARP  = RING * SLOTW;             // 1920 words per warp
constexpr int SMEM_WORDS = OFF_A + 4 * AWARP;    // 14336
constexpr int SMEM_BYTES = SMEM_WORDS * 4;       // 57344 -> 4 CTAs/SM
constexpr int SLOTB = SLOTW * 4;                 // 2560 B

// setup: zero output + convert weights AND node_feats to fp16 layouts
__global__ void setup_kernel(float4* out4, int n4,
                             const float* __restrict__ W1,
                             const float* __restrict__ W2,
                             const float* __restrict__ nf, int nfPairs) {
    int i = blockIdx.x * blockDim.x + threadIdx.x;
    if (i < n4) out4[i] = make_float4(0.f, 0.f, 0.f, 0.f);
    if (i < nfPairs) {
        __half2 h = __floats2half2_rn(nf[2 * i], nf[2 * i + 1]);
        g_nfh[i] = *reinterpret_cast<uint32_t*>(&h);
    }
    if (i < 64 * W1S) {
        int row = i / W1S, c = i % W1S;
        uint32_t v = 0;
        if (c < 64) {
            __half2 h = __floats2half2_rn(W1[row * 128 + 2 * c], W1[row * 128 + 2 * c + 1]);
            v = *reinterpret_cast<uint32_t*>(&h);
        }
        g_W1h[i] = v;
    }
    if (i < 64 * W2S) {
        int row = i / W2S, c = i % W2S;
        uint32_t v = 0;
        if (c < 32) {
            __half2 h = __floats2half2_rn(W2[row * 64 + 2 * c], W2[row * 64 + 2 * c + 1]);
            v = *reinterpret_cast<uint32_t*>(&h);
        }
        g_W2h[i] = v;
    }
}

__device__ __forceinline__ float softplus_b05(float x) {
    float hx = 0.5f * x;
    return (hx > 14.0f) ? x : 2.0f * __logf(1.0f + __expf(hx));
}

__device__ __forceinline__ uint32_t pack_h2(float lo, float hi) {
    __half2 p = __floats2half2_rn(lo, hi);
    return *reinterpret_cast<uint32_t*>(&p);
}

__device__ __forceinline__ void mma_f16(float c[4], const uint32_t a[4],
                                        uint32_t b0, uint32_t b1) {
    asm volatile(
        "mma.sync.aligned.m16n8k16.row.col.f32.f16.f16.f32 "
        "{%0,%1,%2,%3}, {%4,%5,%6,%7}, {%8,%9}, {%0,%1,%2,%3};"
        : "+f"(c[0]), "+f"(c[1]), "+f"(c[2]), "+f"(c[3])
        : "r"(a[0]), "r"(a[1]), "r"(a[2]), "r"(a[3]), "r"(b0), "r"(b1));
}

__device__ __forceinline__ void ldsm_x4(uint32_t r[4], uint32_t addr) {
    asm volatile("ldmatrix.sync.aligned.m8n8.x4.shared.b16 {%0,%1,%2,%3}, [%4];"
                 : "=r"(r[0]), "=r"(r[1]), "=r"(r[2]), "=r"(r[3]) : "r"(addr));
}

__device__ __forceinline__ void cp_async16(uint32_t saddr, const void* gsrc) {
    asm volatile("cp.async.cg.shared.global [%0], [%1], 16;"
                 :: "r"(saddr), "l"(gsrc));
}

__device__ __forceinline__ float2 lds_f2(uint32_t addr) {
    float2 v;
    asm volatile("ld.shared.v2.f32 {%0,%1}, [%2];"
                 : "=f"(v.x), "=f"(v.y) : "r"(addr));
    return v;
}

__device__ __forceinline__ void prefetch_l1(const void* p) {
    asm volatile("prefetch.global.L1 [%0];" :: "l"(p));
}

__global__ void __launch_bounds__(THREADS, 4) cfconv_f16_kernel(
    const float* __restrict__ rbf,   // [E,128]
    const int*   __restrict__ src,   // [E]
    const int*   __restrict__ dst,   // [E]
    const float* __restrict__ b1,    // [64]
    const float* __restrict__ b2,    // [64]
    float*       __restrict__ out,   // [N,64]
    int E, int ntiles)
{
    extern __shared__ uint32_t smem[];

    const int tid  = threadIdx.x;
    const int lane = tid & 31;
    const int warp = tid >> 5;
    const int gr   = lane >> 2;
    const int gc   = lane & 3;
    const int wrow = warp * 32;
    const int gstride = gridDim.x;
    const unsigned FULL = 0xffffffffu;
    const bool odd = (gc & 1);
    const char* rbfB = (const char*)rbf;

    const uint32_t sbase = (uint32_t)__cvta_generic_to_shared(smem);

    // ---- group 0: weights, loaded ONCE per persistent CTA ----
    for (int i = tid; i < 1088; i += THREADS)
        cp_async16(sbase + OFF_W1 * 4 + i * 16, (const char*)g_W1h + i * 16);
    for (int i = tid; i < 576; i += THREADS)
        cp_async16(sbase + OFF_W2 * 4 + i * 16, (const char*)g_W2h + i * 16);
    asm volatile("cp.async.commit_group;");

    // ---- ring geometry: lane covers rows (lane>>2)+8i, 16B each ----
    const uint32_t aBase = sbase + (OFF_A + warp * AWARP) * 4;
    const int lrow = lane >> 2;
    uint32_t sdst4[4];
    #pragma unroll
    for (int i = 0; i < 4; i++)
        sdst4[i] = aBase + ((lrow + 8 * i) * AROW + (lane & 3) * 4) * 4;

    // ---- B-fragment ldsm addresses ----
    const int lb = ((lane >> 4) << 3) | (lane & 7);
    const int sbyt = ((lane >> 3) & 1) * 16;
    uint32_t bW1a[4], bW2a[4];
    #pragma unroll
    for (int p = 0; p < 4; p++) {
        bW1a[p] = sbase + (OFF_W1 + (p * 16 + lb) * W1S) * 4 + sbyt;
        bW2a[p] = sbase + (OFF_W2 + (p * 16 + lb) * W2S) * 4 + sbyt;
    }

    // ---- first tile's row pointers; prime ring with its chunks 0..2 ----
    int tile = blockIdx.x;
    const float* rsrcN[4];
    #pragma unroll
    for (int i = 0; i < 4; i++) {
        long e = (long)tile * BM + wrow + lrow + 8 * i;
        rsrcN[i] = rbf + ((e < E) ? e : 0) * 128 + (lane & 3) * 4;
    }
    #pragma unroll
    for (int c = 0; c < RING; c++) {
        #pragma unroll
        for (int i = 0; i < 4; i++)
            cp_async16(sdst4[i] + c * SLOTB, rsrcN[i] + c * 16);
        asm volatile("cp.async.commit_group;");
    }

    asm volatile("cp.async.wait_group 3;");   // own weight parts done
    __syncthreads();                          // weights visible block-wide

    int slot = 0;   // ring slot of the next chunk to consume

    for (; tile < ntiles; tile += gstride) {
        // current tile streams from rsrcC; compute next tile's pointers now
        const float* rsrcC[4];
        #pragma unroll
        for (int i = 0; i < 4; i++) rsrcC[i] = rsrcN[i];
        {
            int tnext = tile + gstride;
            int tsrc = (tnext < ntiles) ? tnext : tile;   // phantom reload on last
            #pragma unroll
            for (int i = 0; i < 4; i++) {
                long e = (long)tsrc * BM + wrow + lrow + 8 * i;
                rsrcN[i] = rbf + ((e < E) ? e : 0) * 128 + (lane & 3) * 4;
            }
        }

        // lane-private edge indices; prefetch nf row (fp16: one 128B line)
        const long eMine = (long)tile * BM + wrow + lane;
        const bool valMine = (eMine < E);
        int myS = valMine ? src[eMine] : 0;
        int myD = valMine ? dst[eMine] : 0;
        prefetch_l1(g_nfh + (long)myS * 32);

        // ---- GEMM1: 8 chunks of 16; replacement chunk issued each step ----
        float acc[2][8][4] = {};
        #pragma unroll
        for (int c = 0; c < 8; c++) {
            asm volatile("cp.async.wait_group 2;");
            __syncwarp();
            const uint32_t bo = slot * SLOTB;

            uint32_t a[2][4];
            #pragma unroll
            for (int mt = 0; mt < 2; mt++) {
                const uint32_t r0 = aBase + bo + ((mt * 16 + gr) * AROW + 2 * gc) * 4;
                const uint32_t r1 = r0 + 8 * AROW * 4;
                float2 f0 = lds_f2(r0);
                float2 f1 = lds_f2(r1);
                float2 f2 = lds_f2(r0 + 32);
                float2 f3 = lds_f2(r1 + 32);
                a[mt][0] = pack_h2(f0.x, f0.y);
                a[mt][1] = pack_h2(f1.x, f1.y);
                a[mt][2] = pack_h2(f2.x, f2.y);
                a[mt][3] = pack_h2(f3.x, f3.y);
            }

            __syncwarp();   // frags in registers: slot reusable
            {
                const float* const* rs = (c + RING < 8) ? rsrcC : rsrcN;
                const int cc = (c + RING) & 7;
                #pragma unroll
                for (int i = 0; i < 4; i++)
                    cp_async16(sdst4[i] + bo, rs[i] + cc * 16);
                asm volatile("cp.async.commit_group;");
            }
            slot = (slot == RING - 1) ? 0 : slot + 1;

            #pragma unroll
            for (int p = 0; p < 4; p++) {
                uint32_t bb[4];
                ldsm_x4(bb, bW1a[p] + c * 32);
                mma_f16(acc[0][2 * p],     a[0], bb[0], bb[1]);
                mma_f16(acc[1][2 * p],     a[1], bb[0], bb[1]);
                mma_f16(acc[0][2 * p + 1], a[0], bb[2], bb[3]);
                mma_f16(acc[1][2 * p + 1], a[1], bb[2], bb[3]);
            }
        }

        // ---- bias + softplus + pack: GEMM1 C-frags -> GEMM2 A-frags ----
        uint32_t hA[2][4][4];
        #pragma unroll
        for (int kt = 0; kt < 4; kt++) {
            float bA0 = __ldg(b1 + kt * 16 + 2 * gc);
            float bA1 = __ldg(b1 + kt * 16 + 2 * gc + 1);
            float bB0 = __ldg(b1 + kt * 16 + 8 + 2 * gc);
            float bB1 = __ldg(b1 + kt * 16 + 8 + 2 * gc + 1);
            #pragma unroll
            for (int mt = 0; mt < 2; mt++) {
                const float* cA = acc[mt][2 * kt];
                const float* cB = acc[mt][2 * kt + 1];
                hA[mt][kt][0] = pack_h2(softplus_b05(cA[0] + bA0), softplus_b05(cA[1] + bA1));
                hA[mt][kt][1] = pack_h2(softplus_b05(cA[2] + bA0), softplus_b05(cA[3] + bA1));
                hA[mt][kt][2] = pack_h2(softplus_b05(cB[0] + bB0), softplus_b05(cB[1] + bB1));
                hA[mt][kt][3] = pack_h2(softplus_b05(cB[2] + bB0), softplus_b05(cB[3] + bB1));
            }
        }

        // ---- GEMM2: K=64, 4 chunks of 16 ----
        float acc2[2][8][4] = {};
        #pragma unroll
        for (int kt = 0; kt < 4; kt++) {
            #pragma unroll
            for (int p = 0; p < 4; p++) {
                uint32_t bb[4];
                ldsm_x4(bb, bW2a[p] + kt * 32);
                mma_f16(acc2[0][2 * p],     hA[0][kt], bb[0], bb[1]);
                mma_f16(acc2[1][2 * p],     hA[1][kt], bb[0], bb[1]);
                mma_f16(acc2[0][2 * p + 1], hA[0][kt], bb[2], bb[3]);
                mma_f16(acc2[1][2 * p + 1], hA[1][kt], bb[2], bb[3]);
            }
        }

        // ---- epilogue: gate by fp16 nf[src] (L1-warm), vector red scatter ----
        #pragma unroll
        for (int mt = 0; mt < 2; mt++) {
            int rowl = mt * 16 + gr + (odd ? 8 : 0);
            int s = __shfl_sync(FULL, myS, rowl);
            int d = __shfl_sync(FULL, myD, rowl);
            bool valid = ((long)tile * BM + wrow + rowl < E);
            const uint32_t* nfr = g_nfh + (long)s * 32;
            float* outr = out + (long)d * 64;
            #pragma unroll
            for (int nt = 0; nt < 8; nt++) {
                float bc0 = __ldg(b2 + nt * 8 + 2 * gc);
                float bc1 = __ldg(b2 + nt * 8 + 2 * gc + 1);
                float g0 = acc2[mt][nt][0] + bc0, g1 = acc2[mt][nt][1] + bc1;
                float g2 = acc2[mt][nt][2] + bc0, g3 = acc2[mt][nt][3] + bc1;
                float x0 = __shfl_xor_sync(FULL, g0, 1);
                float x1 = __shfl_xor_sync(FULL, g1, 1);
                float x2 = __shfl_xor_sync(FULL, g2, 1);
                float x3 = __shfl_xor_sync(FULL, g3, 1);
                float v0, v1, v2, v3;
                if (odd) { v0 = x2; v1 = x3; v2 = g2; v3 = g3; }
                else     { v0 = g0; v1 = g1; v2 = x0; v3 = x1; }
                int col = nt * 8 + 4 * (gc >> 1);
                if (valid) {
                    uint2 nfp = *(const uint2*)(nfr + (col >> 1));   // 4 halfs
                    float2 lo = __half22float2(*reinterpret_cast<__half2*>(&nfp.x));
                    float2 hi = __half22float2(*reinterpret_cast<__half2*>(&nfp.y));
                    v0 *= lo.x; v1 *= lo.y; v2 *= hi.x; v3 *= hi.y;
                    asm volatile("red.global.add.v4.f32 [%0], {%1,%2,%3,%4};"
                                 :: "l"(outr + col), "f"(v0), "f"(v1), "f"(v2), "f"(v3)
                                 : "memory");
                }
            }
        }
    }
}

extern "C" void kernel_launch(void* const* d_in, const int* in_sizes, int n_in,
                              void* d_out, int out_size) {
    const float* rbf = (const float*)d_in[0];
    const float* nf  = (const float*)d_in[1];
    const int*   src = (const int*)d_in[2];
    const int*   dst = (const int*)d_in[3];
    const float* W1  = (const float*)d_in[4];
    const float* b1  = (const float*)d_in[5];
    const float* W2  = (const float*)d_in[6];
    const float* b2  = (const float*)d_in[7];
    float* out = (float*)d_out;

    const int E = in_sizes[2];
    const int ntiles = (E + BM - 1) / BM;
    const int nfPairs = in_sizes[1] / 2;          // half2 count

    cudaFuncSetAttribute(cfconv_f16_kernel,
                         cudaFuncAttributeMaxDynamicSharedMemorySize, SMEM_BYTES);

    int n4 = out_size / 4;
    int setupN = nfPairs > n4 ? nfPairs : n4;
    setup_kernel<<<(setupN + 255) / 256, 256>>>((float4*)out, n4, W1, W2, nf, nfPairs);

    int grid = 148 * 4;
    if (grid > ntiles) grid = ntiles;
    cfconv_f16_kernel<<<grid, THREADS, SMEM_BYTES>>>(
        rbf, src, dst, b1, b2, out, E, ntiles);
}